// round 4
// baseline (speedup 1.0000x reference)
#include <cuda_runtime.h>
#include <cstdint>

// TreePositionalEncodings — sm_100a, R4: TMA bulk-store path.
//
// out[b, s, j]:
//   s == 0 or s > 1364  -> 0 ;  j >= 1020 -> 0
//   else                -> positions[0, s-1, j/51] * w[j]
// w[j] = tanh(p[j%51])^((j/51)/4) * sqrt((1-tanh^2)*1024/2)
//
// R1-R3 showed two structurally different STG kernels both pin at 4.93 TB/s
// with L1(tex)=67% as the top utilization -> suspected SM-side store-path
// ceiling. R4 switches the write path: compute 16KB tiles into SMEM, drain
// via cp.async.bulk (TMA) with 2-deep pipelining, bypassing per-warp STG.

#define D_MODEL   1024
#define MAX_LEN   2048
#define N_NODES   1364
#define BATCH     32
#define N_FEAT    51
#define N_DW      20
#define STRIP     32                      // rows per block
#define STRIPS_PER_B (MAX_LEN / STRIP)    // 64
#define ROWS_PER_CHUNK 4                  // 16KB per bulk store
#define N_CHUNKS  (STRIP / ROWS_PER_CHUNK)  // 8
#define CHUNK_FLOATS (ROWS_PER_CHUNK * D_MODEL)
#define CHUNK_BYTES  (CHUNK_FLOATS * 4)   // 16384

__device__ __forceinline__ uint32_t smem_u32(const void* ptr) {
    uint32_t a;
    asm("{ .reg .u64 t; cvta.to.shared.u64 t, %1; cvt.u32.u64 %0, t; }"
        : "=r"(a) : "l"(ptr));
    return a;
}

__global__ void __launch_bounds__(256) tree_pos_enc_tma_kernel(
    const float* __restrict__ p,           // [64], first 51 used
    const float* __restrict__ positions,   // [BS, N_NODES, N_DW]; b=0 slice
    float* __restrict__ out)               // [BS, MAX_LEN, D_MODEL]
{
    __shared__ float s_tp[N_FEAT];
    __shared__ float s_norm[N_FEAT];
    __shared__ float s_pos[STRIP][N_DW];
    __shared__ __align__(128) float buf[2][CHUNK_FLOATS];   // 2 x 16KB staging

    const int bx  = blockIdx.x;                        // 0..2047
    const int b   = bx >> 6;                           // batch
    const int s0  = (bx & (STRIPS_PER_B - 1)) * STRIP; // first row of strip
    const int tid = threadIdx.x;                       // 0..255

    if (tid < N_FEAT) {
        float tp = tanhf(p[tid]);
        s_tp[tid]   = tp;
        s_norm[tid] = sqrtf((1.0f - tp * tp) * (0.5f * (float)D_MODEL));
    }
    #pragma unroll
    for (int k = 0; k < (STRIP * N_DW + 255) / 256; k++) {
        int idx = tid + k * 256;
        if (idx < STRIP * N_DW) {
            int r = idx / N_DW, c = idx % N_DW;
            int s = s0 + r;
            float v = 0.0f;
            if (s >= 1 && s <= N_NODES)
                v = positions[(size_t)(s - 1) * N_DW + c];
            s_pos[r][c] = v;
        }
    }
    __syncthreads();

    // Loop-invariant per-thread weights (4 features each).
    const int j = tid * 4;
    float w[4];
    int   dwv[4];
    #pragma unroll
    for (int e = 0; e < 4; e++) {
        int jj = j + e;
        int f  = jj % N_FEAT;
        int dw = jj / N_FEAT;              // 20 only for jj >= 1020 (pad)
        dwv[e] = (dw < N_DW) ? dw : 0;
        float ww = 0.0f;
        if (dw < N_DW) {
            float tp = s_tp[f];
            ww = s_norm[f];
            #pragma unroll 1
            for (int l = 0, lev = dw >> 2; l < lev; l++) ww *= tp;
        }
        w[e] = ww;
    }

    float* gdst_base = out + (size_t)b * (MAX_LEN * D_MODEL)
                           + (size_t)s0 * D_MODEL;

    #pragma unroll 1
    for (int c = 0; c < N_CHUNKS; c++) {
        const int bi = c & 1;

        // Wait for the bulk store that last used this buffer (c-2) to finish
        // READING smem before overwriting it.
        if (c >= 2) {
            if (tid == 0)
                asm volatile("cp.async.bulk.wait_group.read 1;" ::: "memory");
            __syncthreads();
        }

        // Compute 4 rows into the staging buffer (4 x STS.128 per thread).
        #pragma unroll
        for (int r = 0; r < ROWS_PER_CHUNK; r++) {
            const int row = c * ROWS_PER_CHUNK + r;
            float4 v;
            v.x = w[0] * s_pos[row][dwv[0]];
            v.y = w[1] * s_pos[row][dwv[1]];
            v.z = w[2] * s_pos[row][dwv[2]];
            v.w = w[3] * s_pos[row][dwv[3]];
            *reinterpret_cast<float4*>(&buf[bi][r * D_MODEL + j]) = v;
        }
        __syncthreads();

        // One elected thread drains the 16KB tile via TMA bulk store.
        if (tid == 0) {
            asm volatile("fence.proxy.async.shared::cta;" ::: "memory");
            uint32_t src = smem_u32(&buf[bi][0]);
            asm volatile(
                "cp.async.bulk.global.shared::cta.bulk_group [%0], [%1], %2;"
                :: "l"(gdst_base + (size_t)c * CHUNK_FLOATS),
                   "r"(src), "n"(CHUNK_BYTES)
                : "memory");
            asm volatile("cp.async.bulk.commit_group;" ::: "memory");
        }
    }

    // Drain all outstanding bulk stores before exit.
    if (tid == 0)
        asm volatile("cp.async.bulk.wait_group 0;" ::: "memory");
}

extern "C" void kernel_launch(void* const* d_in, const int* in_sizes, int n_in,
                              void* d_out, int out_size) {
    const float* p         = (const float*)d_in[0];   // [64]
    const float* positions = (const float*)d_in[1];   // [32, 1364, 20]
    float* out             = (float*)d_out;           // [32, 2048, 1024]

    tree_pos_enc_tma_kernel<<<BATCH * STRIPS_PER_B, 256>>>(p, positions, out);
}